// round 9
// baseline (speedup 1.0000x reference)
#include <cuda_runtime.h>
#include <cuda_bf16.h>
#include <math.h>
#include <cstdint>

// Problem constants (LocalAttention: B=4, T=2048, C=1024, WIN=16)
#define TT   2048
#define CC   1024
#define HALF 8
#define WW   17
#define MM   8192

// GEMM tiling: CTA tile 128x64, warp tile 32x32, 8 warps (4M x 2N)
// s8 data: stage covers K=64 (64B rows), 2 k32 MMA steps per stage.
#define BM 128
#define BN 64
#define BKK 64                    // s8 K elems per stage
#define NIT (CC / BKK)            // 16 k-iterations
#define ATILE_B 8192              // 128 rows x 64 B
#define BTILE_B 4096              // 64 rows x 64 B
#define STAGE_B (2 * ATILE_B + 2 * BTILE_B)   // 24576 (A1,A2,B1,B2)
#define GEMM_SMEM (4 * STAGE_B)   // 98304
#define GRID_PERSIST 296          // 2 CTAs per SM

// ---------------------------------------------------------------------------
// Scratch (device globals: allocation-free rule)
// ---------------------------------------------------------------------------
__device__ float g_q[MM * CC];
__device__ float g_k[MM * CC];
__device__ float g_v[MM * CC];
__device__ int8_t g_x1[MM * CC];
__device__ int8_t g_x2[MM * CC];
__device__ float  g_xs[MM];
__device__ int8_t g_c1[MM * CC];
__device__ int8_t g_c2[MM * CC];
__device__ float  g_cs[MM];
__device__ int8_t g_w1[4 * CC * CC];   // Wq, Wk, Wv, Wo
__device__ int8_t g_w2[4 * CC * CC];
__device__ float  g_ws[4 * CC];

// ---------------------------------------------------------------------------
// PTX helpers (sm_80+ base-target instructions only)
// ---------------------------------------------------------------------------
__device__ __forceinline__ uint32_t smem_u32(const void* p) {
    uint32_t a;
    asm("{ .reg .u64 t; cvta.to.shared.u64 t, %1; cvt.u32.u64 %0, t; }" : "=r"(a) : "l"(p));
    return a;
}
__device__ __forceinline__ void cp_async16(uint32_t dst, const void* src) {
    asm volatile("cp.async.cg.shared.global [%0], [%1], 16;" :: "r"(dst), "l"(src));
}
__device__ __forceinline__ void cp_commit() { asm volatile("cp.async.commit_group;"); }
template <int N>
__device__ __forceinline__ void cp_wait() { asm volatile("cp.async.wait_group %0;" :: "n"(N)); }

__device__ __forceinline__ void ldsm_x4(uint32_t& r0, uint32_t& r1, uint32_t& r2, uint32_t& r3,
                                        uint32_t addr) {
    asm volatile("ldmatrix.sync.aligned.m8n8.x4.shared.b16 {%0,%1,%2,%3}, [%4];"
                 : "=r"(r0), "=r"(r1), "=r"(r2), "=r"(r3) : "r"(addr));
}
// s8 IMMA: D(s32) += A(s8, m16k32 row) * B(s8, k32n8 col)
__device__ __forceinline__ void mma_s8(int* d, const uint32_t* a, uint32_t b0, uint32_t b1) {
    asm volatile(
        "mma.sync.aligned.m16n8k32.row.col.s32.s8.s8.s32 "
        "{%0,%1,%2,%3}, {%4,%5,%6,%7}, {%8,%9}, {%0,%1,%2,%3};"
        : "+r"(d[0]), "+r"(d[1]), "+r"(d[2]), "+r"(d[3])
        : "r"(a[0]), "r"(a[1]), "r"(a[2]), "r"(a[3]), "r"(b0), "r"(b1));
}

// Swizzle on 64B logical rows (conflict-free ldmatrix + STS16)
#define SWZ(off) ((off) ^ (((off) >> 3) & 0x70))

__device__ __forceinline__ uint32_t ldsm_addr(uint32_t tile_base, int row0, int chunk0, int lane) {
    int row   = row0 + (lane & 15);
    int chunk = chunk0 + (lane >> 4);
    uint32_t off = (uint32_t)row * 64 + (uint32_t)chunk * 16;
    return tile_base + SWZ(off);
}

// ---------------------------------------------------------------------------
// fp32 -> 2-term s8 quantization, one warp per row of 1024.
// x ~= s * (A1 + A2/256), s = rowmax/127 stored to sc[row].
// Up to 4 sources, each rowsPerSrc rows.
// ---------------------------------------------------------------------------
__global__ __launch_bounds__(256)
void quant_rows(const float* __restrict__ s0, const float* __restrict__ s1,
                const float* __restrict__ s2, const float* __restrict__ s3,
                int8_t* __restrict__ q1, int8_t* __restrict__ q2,
                float* __restrict__ sc, int rowsPerSrc)
{
    const int warp = threadIdx.x >> 5;
    const int lane = threadIdx.x & 31;
    const int r = blockIdx.x * 8 + warp;
    const float* srcs[4] = {s0, s1, s2, s3};
    const float* src = srcs[r / rowsPerSrc] + (size_t)(r % rowsPerSrc) * CC;

    float v[32];
    float m = 0.f;
#pragma unroll
    for (int j = 0; j < 8; j++) {
        float4 f = *(const float4*)(src + j * 128 + lane * 4);
        v[j*4+0] = f.x; v[j*4+1] = f.y; v[j*4+2] = f.z; v[j*4+3] = f.w;
        m = fmaxf(m, fmaxf(fmaxf(fabsf(f.x), fabsf(f.y)), fmaxf(fabsf(f.z), fabsf(f.w))));
    }
#pragma unroll
    for (int o = 16; o; o >>= 1) m = fmaxf(m, __shfl_xor_sync(0xffffffffu, m, o));
    m = fmaxf(m, 1e-20f);
    if (lane == 0) sc[r] = m * (1.f / 127.f);
    const float inv = 127.f / m;

#pragma unroll
    for (int j = 0; j < 8; j++) {
        char c1[4], c2[4];
#pragma unroll
        for (int i = 0; i < 4; i++) {
            float qv = v[j*4+i] * inv;              // in [-127, 127]
            int a1 = __float2int_rn(qv);
            int a2 = __float2int_rn((qv - (float)a1) * 256.f);
            a2 = max(-127, min(127, a2));
            c1[i] = (char)a1; c2[i] = (char)a2;
        }
        const size_t o = (size_t)r * CC + j * 128 + lane * 4;
        *(char4*)(q1 + o) = make_char4(c1[0], c1[1], c1[2], c1[3]);
        *(char4*)(q2 + o) = make_char4(c2[0], c2[1], c2[2], c2[3]);
    }
}

// ---------------------------------------------------------------------------
// Persistent s8 2-term NT GEMM, 128x64 CTA tile, 2 CTAs/SM.
// out[m,n] = sa[m]*sb[n]*(P1 + P2/256) + bias[n], P1=A1B1, P2=A1B2+A2B1.
// nblk = weight 64-col blocks (48 fused QKV, 16 Wo); which = nb>>4.
// ---------------------------------------------------------------------------
__global__ __launch_bounds__(256, 2)
void gemm_s8(const int8_t* __restrict__ A1, const int8_t* __restrict__ A2,
             const float* __restrict__ sa,
             const int8_t* __restrict__ W1, const int8_t* __restrict__ W2,
             const float* __restrict__ sb,
             const float* __restrict__ b0, const float* __restrict__ b1,
             const float* __restrict__ b2,
             float* __restrict__ o0, float* __restrict__ o1, float* __restrict__ o2,
             int ntiles, int nblk)
{
    extern __shared__ char sm[];
    const uint32_t sbase = smem_u32(sm);
    const int tid   = threadIdx.x;
    const int lane  = tid & 31;
    const int warp  = tid >> 5;
    const int warpM = warp >> 1;     // 0..3 -> 32-row slice
    const int warpN = warp & 1;      // 0..1 -> 32-col slice

    // A loader: row = tid/2 (128 rows of 64B), two 16B chunks at (tid&1)*2+{0,1}
    const int larow = tid >> 1;
    const int lac0  = (tid & 1) * 2;
    uint32_t daphys[2];
#pragma unroll
    for (int i = 0; i < 2; i++) {
        uint32_t off = (uint32_t)larow * 64 + (uint32_t)(lac0 + i) * 16;
        daphys[i] = SWZ(off);
    }
    // B loader: row = tid/4 (64 rows), one 16B chunk at tid&3
    const int lbrow = tid >> 2;
    const int lbc   = tid & 3;
    const uint32_t dbphys = SWZ((uint32_t)lbrow * 64 + (uint32_t)lbc * 16);

    for (int tile = blockIdx.x; tile < ntiles; tile += gridDim.x) {
        const int mb = tile / nblk;
        const int nb = tile - mb * nblk;
        const int bm = mb * BM;
        const int which = nb >> 4;
        const int col0  = (nb & 15) * BN;
        const float* bias = (which == 0) ? b0 : ((which == 1) ? b1 : b2);
        float* Cout       = (which == 0) ? o0 : ((which == 1) ? o1 : o2);

        const int8_t* gA[2] = {
            A1 + (size_t)(bm + larow) * CC,
            A2 + (size_t)(bm + larow) * CC
        };
        const int8_t* gB[2] = {
            W1 + (size_t)(nb * BN + lbrow) * CC,
            W2 + (size_t)(nb * BN + lbrow) * CC
        };

#define ISSUE_STAGE(s, kc) do { \
    uint32_t stg_ = sbase + (uint32_t)(s) * STAGE_B; \
    _Pragma("unroll") \
    for (int h_ = 0; h_ < 2; h_++) { \
        _Pragma("unroll") \
        for (int i_ = 0; i_ < 2; i_++) { \
            cp_async16(stg_ + h_ * ATILE_B + daphys[i_], gA[h_] + (kc) + (lac0 + i_) * 16); \
        } \
        cp_async16(stg_ + 2 * ATILE_B + h_ * BTILE_B + dbphys, gB[h_] + (kc) + lbc * 16); \
    } \
    cp_commit(); \
} while (0)

        int p1[2][4][4], p2[2][4][4];
#pragma unroll
        for (int mt = 0; mt < 2; mt++)
#pragma unroll
            for (int nt = 0; nt < 4; nt++)
#pragma unroll
                for (int r = 0; r < 4; r++) { p1[mt][nt][r] = 0; p2[mt][nt][r] = 0; }

        ISSUE_STAGE(0, 0);
        ISSUE_STAGE(1, 64);
        ISSUE_STAGE(2, 128);

        for (int it = 0; it < NIT; it++) {
            cp_wait<2>();
            __syncthreads();
            if (it + 3 < NIT) { ISSUE_STAGE((it + 3) & 3, (it + 3) * BKK); }
            else              { cp_commit(); }

            const uint32_t stg = sbase + (uint32_t)(it & 3) * STAGE_B;
#pragma unroll
            for (int g = 0; g < 2; g++) {        // two k32 steps per stage
                uint32_t afr[2][2][4];           // [mt][term][reg]
#pragma unroll
                for (int mt = 0; mt < 2; mt++)
#pragma unroll
                    for (int t = 0; t < 2; t++) {
                        uint32_t ad = ldsm_addr(stg + t * ATILE_B,
                                                warpM * 32 + mt * 16, 2 * g, lane);
                        ldsm_x4(afr[mt][t][0], afr[mt][t][1], afr[mt][t][2], afr[mt][t][3], ad);
                    }
                uint32_t bfr[2][2][4];           // [term][gp][reg]
#pragma unroll
                for (int t = 0; t < 2; t++)
#pragma unroll
                    for (int gp = 0; gp < 2; gp++) {
                        uint32_t ad = ldsm_addr(stg + 2 * ATILE_B + t * BTILE_B,
                                                warpN * 32 + gp * 16, 2 * g, lane);
                        ldsm_x4(bfr[t][gp][0], bfr[t][gp][1], bfr[t][gp][2], bfr[t][gp][3], ad);
                    }
#pragma unroll
                for (int mt = 0; mt < 2; mt++)
#pragma unroll
                    for (int gp = 0; gp < 2; gp++) {
                        // n8 even half: k chunks {r0, r2}
                        mma_s8(p1[mt][gp * 2 + 0], afr[mt][0], bfr[0][gp][0], bfr[0][gp][2]);
                        mma_s8(p2[mt][gp * 2 + 0], afr[mt][0], bfr[1][gp][0], bfr[1][gp][2]);
                        mma_s8(p2[mt][gp * 2 + 0], afr[mt][1], bfr[0][gp][0], bfr[0][gp][2]);
                        // n8 odd half: {r1, r3}
                        mma_s8(p1[mt][gp * 2 + 1], afr[mt][0], bfr[0][gp][1], bfr[0][gp][3]);
                        mma_s8(p2[mt][gp * 2 + 1], afr[mt][0], bfr[1][gp][1], bfr[1][gp][3]);
                        mma_s8(p2[mt][gp * 2 + 1], afr[mt][1], bfr[0][gp][1], bfr[0][gp][3]);
                    }
            }
        }

        // Epilogue: dequant + bias + fp32 store (warp tile 32x32)
#pragma unroll
        for (int mt = 0; mt < 2; mt++) {
            const int m0 = bm + warpM * 32 + mt * 16 + (lane >> 2);
            const float sa0 = sa[m0], sa1 = sa[m0 + 8];
#pragma unroll
            for (int nt = 0; nt < 4; nt++) {
                const int local = warpN * 32 + nt * 8 + (lane & 3) * 2;
                const int col = col0 + local;
                const int wr  = nb * BN + local;
                const float sb0 = sb[wr], sb1 = sb[wr + 1];
                const float c0 = bias[col], c1 = bias[col + 1];
                float v00 = sa0 * sb0 * ((float)p1[mt][nt][0] + (float)p2[mt][nt][0] * (1.f/256.f)) + c0;
                float v01 = sa0 * sb1 * ((float)p1[mt][nt][1] + (float)p2[mt][nt][1] * (1.f/256.f)) + c1;
                float v10 = sa1 * sb0 * ((float)p1[mt][nt][2] + (float)p2[mt][nt][2] * (1.f/256.f)) + c0;
                float v11 = sa1 * sb1 * ((float)p1[mt][nt][3] + (float)p2[mt][nt][3] * (1.f/256.f)) + c1;
                *(float2*)(Cout + (size_t)m0 * CC + col)       = make_float2(v00, v01);
                *(float2*)(Cout + (size_t)(m0 + 8) * CC + col) = make_float2(v10, v11);
            }
        }
#undef ISSUE_STAGE
    }
}

// ---------------------------------------------------------------------------
// Local windowed attention; writes ctx directly as 2-term s8 + row scale.
// ---------------------------------------------------------------------------
__global__ __launch_bounds__(128)
void local_attn(const float* __restrict__ q, const float* __restrict__ k,
                const float* __restrict__ v,
                int8_t* __restrict__ c1, int8_t* __restrict__ c2,
                float* __restrict__ cs)
{
    const int bt   = blockIdx.x;
    const int t    = bt & (TT - 1);
    const int tid  = threadIdx.x;
    const int warp = tid >> 5;
    const int lane = tid & 31;

    __shared__ float red[WW][4];
    __shared__ float wgt[WW];
    __shared__ float smax[4];

    const float* qrow = q + (size_t)bt * CC;
    float qreg[8];
#pragma unroll
    for (int i = 0; i < 8; i++) qreg[i] = qrow[tid + i * 128];

#pragma unroll
    for (int w = 0; w < WW; w++) {
        const int dt = w - HALF;
        const int tt = t + dt;
        float p = 0.f;
        if (tt >= 0 && tt < TT) {
            const float* krow = k + (size_t)(bt + dt) * CC;
#pragma unroll
            for (int i = 0; i < 8; i++) p += qreg[i] * krow[tid + i * 128];
        }
#pragma unroll
        for (int o = 16; o; o >>= 1) p += __shfl_xor_sync(0xffffffffu, p, o);
        if (lane == 0) red[w][warp] = p;
    }
    __syncthreads();

    if (tid == 0) {
        float s[WW];
        float mx = -1e30f;
#pragma unroll
        for (int w = 0; w < WW; w++) {
            const int tt = t + w - HALF;
            if (tt >= 0 && tt < TT) {
                s[w] = (red[w][0] + red[w][1] + red[w][2] + red[w][3]) * 0.03125f;
                mx = fmaxf(mx, s[w]);
            } else {
                s[w] = -3.0e38f;
            }
        }
        float sum = 0.f;
#pragma unroll
        for (int w = 0; w < WW; w++) {
            float e = (s[w] > -1.0e38f) ? expf(s[w] - mx) : 0.f;
            wgt[w] = e;
            sum += e;
        }
        const float inv = 1.f / sum;
#pragma unroll
        for (int w = 0; w < WW; w++) wgt[w] *= inv;
    }
    __syncthreads();

    float acc[8];
#pragma unroll
    for (int i = 0; i < 8; i++) acc[i] = 0.f;

#pragma unroll
    for (int w = 0; w < WW; w++) {
        const int dt = w - HALF;
        const int tt = t + dt;
        if (tt < 0 || tt >= TT) continue;
        const float a = wgt[w];
        const float* vrow = v + (size_t)(bt + dt) * CC;
#pragma unroll
        for (int i = 0; i < 8; i++) acc[i] += a * vrow[tid + i * 128];
    }

    // Row max for quantization
    float m = 0.f;
#pragma unroll
    for (int i = 0; i < 8; i++) m = fmaxf(m, fabsf(acc[i]));
#pragma unroll
    for (int o = 16; o; o >>= 1) m = fmaxf(m, __shfl_xor_sync(0xffffffffu, m, o));
    if (lane == 0) smax[warp] = m;
    __syncthreads();
    m = fmaxf(fmaxf(smax[0], smax[1]), fmaxf(smax[2], smax[3]));
    m = fmaxf(m, 1e-20f);
    if (tid == 0) cs[bt] = m * (1.f / 127.f);
    const float inv = 127.f / m;

    int8_t* r1 = c1 + (size_t)bt * CC;
    int8_t* r2 = c2 + (size_t)bt * CC;
#pragma unroll
    for (int i = 0; i < 8; i++) {
        float qv = acc[i] * inv;
        int a1 = __float2int_rn(qv);
        int a2 = __float2int_rn((qv - (float)a1) * 256.f);
        a2 = max(-127, min(127, a2));
        r1[tid + i * 128] = (int8_t)a1;
        r2[tid + i * 128] = (int8_t)a2;
    }
}

// ---------------------------------------------------------------------------
// Launch (5 launches; 2 and 4 are the GEMMs)
// ---------------------------------------------------------------------------
extern "C" void kernel_launch(void* const* d_in, const int* in_sizes, int n_in,
                              void* d_out, int out_size)
{
    const float* x  = (const float*)d_in[0];
    const float* Wq = (const float*)d_in[1];
    const float* bq = (const float*)d_in[2];
    const float* Wk = (const float*)d_in[3];
    const float* bk = (const float*)d_in[4];
    const float* Wv = (const float*)d_in[5];
    const float* bv = (const float*)d_in[6];
    const float* Wo = (const float*)d_in[7];
    const float* bo = (const float*)d_in[8];

    float *q, *k, *v, *xs, *cs, *ws;
    int8_t *x1, *x2, *c1, *c2, *w1, *w2;
    cudaGetSymbolAddress((void**)&q,  g_q);
    cudaGetSymbolAddress((void**)&k,  g_k);
    cudaGetSymbolAddress((void**)&v,  g_v);
    cudaGetSymbolAddress((void**)&x1, g_x1);
    cudaGetSymbolAddress((void**)&x2, g_x2);
    cudaGetSymbolAddress((void**)&xs, g_xs);
    cudaGetSymbolAddress((void**)&c1, g_c1);
    cudaGetSymbolAddress((void**)&c2, g_c2);
    cudaGetSymbolAddress((void**)&cs, g_cs);
    cudaGetSymbolAddress((void**)&w1, g_w1);
    cudaGetSymbolAddress((void**)&w2, g_w2);
    cudaGetSymbolAddress((void**)&ws, g_ws);

    cudaFuncSetAttribute(gemm_s8, cudaFuncAttributeMaxDynamicSharedMemorySize, GEMM_SMEM);

    // 0: quantize x (8192 rows, 1 source)
    quant_rows<<<MM / 8, 256>>>(x, x, x, x, x1, x2, xs, MM);
    // 1: quantize Wq|Wk|Wv|Wo (4096 rows, 4 sources)
    quant_rows<<<4 * CC / 8, 256>>>(Wq, Wk, Wv, Wo, w1, w2, ws, CC);
    // 2: fused QKV GEMM (persistent, 3072 tiles, nblk=48)
    gemm_s8<<<GRID_PERSIST, 256, GEMM_SMEM>>>(x1, x2, xs, w1, w2, ws,
                                              bq, bk, bv, q, k, v,
                                              (MM / BM) * 48, 48);
    // 3: attention (writes quantized ctx)
    local_attn<<<MM, 128>>>(q, k, v, c1, c2, cs);
    // 4: output projection (persistent, 1024 tiles, nblk=16)
    gemm_s8<<<GRID_PERSIST, 256, GEMM_SMEM>>>(c1, c2, cs,
                                              w1 + 3 * (size_t)CC * CC, w2 + 3 * (size_t)CC * CC,
                                              ws + 3 * CC,
                                              bo, bo, bo,
                                              (float*)d_out, (float*)d_out, (float*)d_out,
                                              (MM / BM) * 16, 16);
}

// round 10
// speedup vs baseline: 1.8563x; 1.8563x over previous
#include <cuda_runtime.h>
#include <cuda_bf16.h>
#include <math.h>
#include <cstdint>

// Problem constants (LocalAttention: B=4, T=2048, C=1024, WIN=16)
#define BB   4
#define TT   2048
#define CC   1024
#define HALF 8
#define WW   17
#define MM   8192
#define GG   8                    // t-positions per attention block

// GEMM tiling: CTA tile 128x64, warp tile 32x32, 8 warps (4M x 2N)
#define BM 128
#define BN 64
#define BKK 32                    // bf16 K elems per stage
#define NIT (CC / BKK)            // 32 k-iterations
#define ATILE_B 8192              // 128 rows x 32 bf16 x 2B
#define BTILE_B 4096              // 64 rows x 32 bf16 x 2B
#define STAGE_B (2 * ATILE_B + 2 * BTILE_B)   // 24576
#define GEMM_SMEM (4 * STAGE_B)   // 98304
#define GRID_PERSIST 296          // 2 CTAs per SM
#define ATTN_SMEM (2 * 24 * CC * 4)   // 196608 (k + v windows)

// ---------------------------------------------------------------------------
// Scratch (device globals: allocation-free rule)
// ---------------------------------------------------------------------------
__device__ float g_q[MM * CC];
__device__ float g_k[MM * CC];
__device__ float g_v[MM * CC];
__device__ __nv_bfloat16 g_x_hi[MM * CC];
__device__ __nv_bfloat16 g_x_lo[MM * CC];
__device__ __nv_bfloat16 g_ctx_hi[MM * CC];
__device__ __nv_bfloat16 g_ctx_lo[MM * CC];
__device__ __nv_bfloat16 g_w_hi[4 * CC * CC];   // Wq, Wk, Wv, Wo
__device__ __nv_bfloat16 g_w_lo[4 * CC * CC];

// ---------------------------------------------------------------------------
// PTX helpers (sm_80+ base-target instructions only)
// ---------------------------------------------------------------------------
__device__ __forceinline__ uint32_t smem_u32(const void* p) {
    uint32_t a;
    asm("{ .reg .u64 t; cvta.to.shared.u64 t, %1; cvt.u32.u64 %0, t; }" : "=r"(a) : "l"(p));
    return a;
}
__device__ __forceinline__ void cp_async16(uint32_t dst, const void* src) {
    asm volatile("cp.async.cg.shared.global [%0], [%1], 16;" :: "r"(dst), "l"(src));
}
__device__ __forceinline__ void cp_commit() { asm volatile("cp.async.commit_group;"); }
template <int N>
__device__ __forceinline__ void cp_wait() { asm volatile("cp.async.wait_group %0;" :: "n"(N)); }

__device__ __forceinline__ void ldsm_x4(uint32_t& r0, uint32_t& r1, uint32_t& r2, uint32_t& r3,
                                        uint32_t addr) {
    asm volatile("ldmatrix.sync.aligned.m8n8.x4.shared.b16 {%0,%1,%2,%3}, [%4];"
                 : "=r"(r0), "=r"(r1), "=r"(r2), "=r"(r3) : "r"(addr));
}
__device__ __forceinline__ void mma_bf16(float* d, const uint32_t* a, uint32_t b0, uint32_t b1) {
    asm volatile(
        "mma.sync.aligned.m16n8k16.row.col.f32.bf16.bf16.f32 "
        "{%0,%1,%2,%3}, {%4,%5,%6,%7}, {%8,%9}, {%0,%1,%2,%3};"
        : "+f"(d[0]), "+f"(d[1]), "+f"(d[2]), "+f"(d[3])
        : "r"(a[0]), "r"(a[1]), "r"(a[2]), "r"(a[3]), "r"(b0), "r"(b1));
}

// Swizzle on 64B logical rows (conflict-free ldmatrix + STS16)
#define SWZ(off) ((off) ^ (((off) >> 3) & 0x70))

__device__ __forceinline__ uint32_t ldsm_addr(uint32_t tile_base, int row0, int chunk0, int lane) {
    int row   = row0 + (lane & 15);
    int chunk = chunk0 + (lane >> 4);
    uint32_t off = (uint32_t)row * 64 + (uint32_t)chunk * 16;
    return tile_base + SWZ(off);
}

// ---------------------------------------------------------------------------
// fp32 -> bf16 hi/lo split. blockIdx.y selects among up to 4 sources.
// ---------------------------------------------------------------------------
__global__ __launch_bounds__(256)
void split_bf16(const float* __restrict__ s0, const float* __restrict__ s1,
                const float* __restrict__ s2, const float* __restrict__ s3,
                __nv_bfloat16* __restrict__ hi, __nv_bfloat16* __restrict__ lo, int n4)
{
    const int w = blockIdx.y;
    const float* srcs[4] = {s0, s1, s2, s3};
    const float* src = srcs[w];
    int i = blockIdx.x * blockDim.x + threadIdx.x;
    if (i >= n4) return;
    float4 v = ((const float4*)src)[i];
    float f[4] = {v.x, v.y, v.z, v.w};
    __nv_bfloat16 h[4], l[4];
#pragma unroll
    for (int j = 0; j < 4; j++) {
        h[j] = __float2bfloat16(f[j]);
        l[j] = __float2bfloat16(f[j] - __bfloat162float(h[j]));
    }
    const size_t o = (size_t)w * n4 + i;
    ((ushort4*)hi)[o] = make_ushort4(*(unsigned short*)&h[0], *(unsigned short*)&h[1],
                                     *(unsigned short*)&h[2], *(unsigned short*)&h[3]);
    ((ushort4*)lo)[o] = make_ushort4(*(unsigned short*)&l[0], *(unsigned short*)&l[1],
                                     *(unsigned short*)&l[2], *(unsigned short*)&l[3]);
}

// ---------------------------------------------------------------------------
// Persistent bf16x3 NT GEMM, 128x64 CTA tile, 2 CTAs/SM.  (identical to R8)
// out[m,n] = sum_k A[m,k]*W[n,k] + bias[n].
// nblk = weight 64-col blocks (48 for fused QKV, 16 for Wo); which = nb>>4.
// ---------------------------------------------------------------------------
__global__ __launch_bounds__(256, 2)
void gemm_bf16x3(const __nv_bfloat16* __restrict__ Ahi, const __nv_bfloat16* __restrict__ Alo,
                 const __nv_bfloat16* __restrict__ Whi, const __nv_bfloat16* __restrict__ Wlo,
                 const float* __restrict__ b0, const float* __restrict__ b1,
                 const float* __restrict__ b2,
                 float* __restrict__ o0, float* __restrict__ o1, float* __restrict__ o2,
                 int ntiles, int nblk)
{
    extern __shared__ char sm[];
    const uint32_t sbase = smem_u32(sm);
    const int tid   = threadIdx.x;
    const int lane  = tid & 31;
    const int warp  = tid >> 5;
    const int warpM = warp >> 1;
    const int warpN = warp & 1;

    const int larow = tid >> 1;
    const int lac0  = (tid & 1) * 2;
    uint32_t daphys[2];
#pragma unroll
    for (int i = 0; i < 2; i++) {
        uint32_t off = (uint32_t)larow * 64 + (uint32_t)(lac0 + i) * 16;
        daphys[i] = SWZ(off);
    }
    const int lbrow = tid >> 2;
    const int lbc   = tid & 3;
    const uint32_t dbphys = SWZ((uint32_t)lbrow * 64 + (uint32_t)lbc * 16);

    for (int tile = blockIdx.x; tile < ntiles; tile += gridDim.x) {
        const int mb = tile / nblk;
        const int nb = tile - mb * nblk;
        const int bm = mb * BM;
        const int which = nb >> 4;
        const int col0  = (nb & 15) * BN;
        const float* bias = (which == 0) ? b0 : ((which == 1) ? b1 : b2);
        float* Cout       = (which == 0) ? o0 : ((which == 1) ? o1 : o2);

        const __nv_bfloat16* gA[2] = {
            Ahi + (size_t)(bm + larow) * CC,
            Alo + (size_t)(bm + larow) * CC
        };
        const __nv_bfloat16* gB[2] = {
            Whi + (size_t)(nb * BN + lbrow) * CC,
            Wlo + (size_t)(nb * BN + lbrow) * CC
        };

#define ISSUE_STAGE(s, kc) do { \
    uint32_t stg_ = sbase + (uint32_t)(s) * STAGE_B; \
    _Pragma("unroll") \
    for (int h_ = 0; h_ < 2; h_++) { \
        _Pragma("unroll") \
        for (int i_ = 0; i_ < 2; i_++) { \
            cp_async16(stg_ + h_ * ATILE_B + daphys[i_], gA[h_] + (kc) + (lac0 + i_) * 8); \
        } \
        cp_async16(stg_ + 2 * ATILE_B + h_ * BTILE_B + dbphys, gB[h_] + (kc) + lbc * 8); \
    } \
    cp_commit(); \
} while (0)

        float acc[2][4][4];
#pragma unroll
        for (int mt = 0; mt < 2; mt++)
#pragma unroll
            for (int nt = 0; nt < 4; nt++)
#pragma unroll
                for (int r = 0; r < 4; r++) acc[mt][nt][r] = 0.f;

        ISSUE_STAGE(0, 0);
        ISSUE_STAGE(1, 32);
        ISSUE_STAGE(2, 64);

        for (int it = 0; it < NIT; it++) {
            cp_wait<2>();
            __syncthreads();
            if (it + 3 < NIT) { ISSUE_STAGE((it + 3) & 3, (it + 3) * BKK); }
            else              { cp_commit(); }

            const uint32_t stg = sbase + (uint32_t)(it & 3) * STAGE_B;
#pragma unroll
            for (int g = 0; g < 2; g++) {
                uint32_t afr[2][2][4];
#pragma unroll
                for (int mt = 0; mt < 2; mt++)
#pragma unroll
                    for (int hl = 0; hl < 2; hl++) {
                        uint32_t ad = ldsm_addr(stg + hl * ATILE_B,
                                                warpM * 32 + mt * 16, 2 * g, lane);
                        ldsm_x4(afr[mt][hl][0], afr[mt][hl][1], afr[mt][hl][2], afr[mt][hl][3], ad);
                    }
                uint32_t bfr[2][2][4];
#pragma unroll
                for (int hl = 0; hl < 2; hl++)
#pragma unroll
                    for (int gp = 0; gp < 2; gp++) {
                        uint32_t ad = ldsm_addr(stg + 2 * ATILE_B + hl * BTILE_B,
                                                warpN * 32 + gp * 16, 2 * g, lane);
                        ldsm_x4(bfr[hl][gp][0], bfr[hl][gp][1], bfr[hl][gp][2], bfr[hl][gp][3], ad);
                    }
#pragma unroll
                for (int mt = 0; mt < 2; mt++)
#pragma unroll
                    for (int gp = 0; gp < 2; gp++) {
                        mma_bf16(acc[mt][gp * 2 + 0], afr[mt][0], bfr[0][gp][0], bfr[0][gp][2]);
                        mma_bf16(acc[mt][gp * 2 + 1], afr[mt][0], bfr[0][gp][1], bfr[0][gp][3]);
                        mma_bf16(acc[mt][gp * 2 + 0], afr[mt][0], bfr[1][gp][0], bfr[1][gp][2]);
                        mma_bf16(acc[mt][gp * 2 + 1], afr[mt][0], bfr[1][gp][1], bfr[1][gp][3]);
                        mma_bf16(acc[mt][gp * 2 + 0], afr[mt][1], bfr[0][gp][0], bfr[0][gp][2]);
                        mma_bf16(acc[mt][gp * 2 + 1], afr[mt][1], bfr[0][gp][1], bfr[0][gp][3]);
                    }
            }
        }

#pragma unroll
        for (int mt = 0; mt < 2; mt++) {
            const int row0 = bm + warpM * 32 + mt * 16 + (lane >> 2);
#pragma unroll
            for (int nt = 0; nt < 4; nt++) {
                const int col = col0 + warpN * 32 + nt * 8 + (lane & 3) * 2;
                const float c0 = bias[col], c1 = bias[col + 1];
                float2 v0 = make_float2(acc[mt][nt][0] + c0, acc[mt][nt][1] + c1);
                float2 v1 = make_float2(acc[mt][nt][2] + c0, acc[mt][nt][3] + c1);
                *(float2*)(Cout + (size_t)row0 * CC + col)       = v0;
                *(float2*)(Cout + (size_t)(row0 + 8) * CC + col) = v1;
            }
        }
#undef ISSUE_STAGE
    }
}

// ---------------------------------------------------------------------------
// Smem-tiled local attention: one block = 8 consecutive t positions, sharing
// the 24-row k/v window in shared memory. One warp per t.
// Writes ctx directly as bf16 hi/lo pair.
// ---------------------------------------------------------------------------
__global__ __launch_bounds__(256)
void local_attn(const float* __restrict__ q, const float* __restrict__ k,
                const float* __restrict__ v,
                __nv_bfloat16* __restrict__ ch, __nv_bfloat16* __restrict__ cl)
{
    extern __shared__ float sh[];
    float* ks = sh;                 // [24][CC]
    float* vs = sh + 24 * CC;       // [24][CC]
    __shared__ float sscore[GG][WW];
    __shared__ float swgt[GG][WW];

    const int b    = blockIdx.y;
    const int t0   = blockIdx.x * GG;
    const int tid  = threadIdx.x;
    const int warp = tid >> 5;
    const int lane = tid & 31;

    // Stage k/v rows [t0-8, t0+15] (24 rows); each thread copies 4 floats/row.
#pragma unroll 4
    for (int r = 0; r < 24; r++) {
        const int trow = t0 - HALF + r;
        if (trow < 0 || trow >= TT) continue;
        const size_t g = ((size_t)b * TT + trow) * CC;
        ((float4*)(ks + r * CC))[tid] = ((const float4*)(k + g))[tid];
        ((float4*)(vs + r * CC))[tid] = ((const float4*)(v + g))[tid];
    }
    __syncthreads();

    // Warp handles t = t0 + warp.
    const int t = t0 + warp;
    const size_t btrow = (size_t)b * TT + t;

    float4 qv[8];
    const float4* qrow = (const float4*)(q + btrow * CC);
#pragma unroll
    for (int i = 0; i < 8; i++) qv[i] = qrow[lane + i * 32];

    // Scores
#pragma unroll
    for (int w = 0; w < WW; w++) {
        const int tt = t + w - HALF;
        float p = 0.f;
        if (tt >= 0 && tt < TT) {
            const float4* kr = (const float4*)(ks + (warp + w) * CC);
#pragma unroll
            for (int i = 0; i < 8; i++) {
                float4 kf = kr[lane + i * 32];
                p += qv[i].x * kf.x + qv[i].y * kf.y + qv[i].z * kf.z + qv[i].w * kf.w;
            }
        }
#pragma unroll
        for (int o = 16; o; o >>= 1) p += __shfl_xor_sync(0xffffffffu, p, o);
        if (lane == 0) sscore[warp][w] = p;
    }
    __syncwarp();

    // Softmax (lane 0 of each warp)
    if (lane == 0) {
        float s[WW];
        float mx = -1e30f;
#pragma unroll
        for (int w = 0; w < WW; w++) {
            const int tt = t + w - HALF;
            if (tt >= 0 && tt < TT) {
                s[w] = sscore[warp][w] * 0.03125f;
                mx = fmaxf(mx, s[w]);
            } else {
                s[w] = -3.0e38f;
            }
        }
        float sum = 0.f;
#pragma unroll
        for (int w = 0; w < WW; w++) {
            float e = (s[w] > -1.0e38f) ? expf(s[w] - mx) : 0.f;
            swgt[warp][w] = e;
            sum += e;
        }
        const float inv = 1.f / sum;
#pragma unroll
        for (int w = 0; w < WW; w++) swgt[warp][w] *= inv;
    }
    __syncwarp();

    // Weighted V sum
    float4 acc[8];
#pragma unroll
    for (int i = 0; i < 8; i++) acc[i] = make_float4(0.f, 0.f, 0.f, 0.f);
#pragma unroll
    for (int w = 0; w < WW; w++) {
        const int tt = t + w - HALF;
        if (tt < 0 || tt >= TT) continue;
        const float a = swgt[warp][w];
        const float4* vr = (const float4*)(vs + (warp + w) * CC);
#pragma unroll
        for (int i = 0; i < 8; i++) {
            float4 vf = vr[lane + i * 32];
            acc[i].x += a * vf.x; acc[i].y += a * vf.y;
            acc[i].z += a * vf.z; acc[i].w += a * vf.w;
        }
    }

    // Store ctx as bf16 hi/lo (4 bf16 = 8B per thread per i)
    ushort4* hrow = (ushort4*)(ch + btrow * CC);
    ushort4* lrow = (ushort4*)(cl + btrow * CC);
#pragma unroll
    for (int i = 0; i < 8; i++) {
        float f[4] = {acc[i].x, acc[i].y, acc[i].z, acc[i].w};
        unsigned short h[4], l[4];
#pragma unroll
        for (int c = 0; c < 4; c++) {
            __nv_bfloat16 hb = __float2bfloat16(f[c]);
            __nv_bfloat16 lb = __float2bfloat16(f[c] - __bfloat162float(hb));
            h[c] = *(unsigned short*)&hb;
            l[c] = *(unsigned short*)&lb;
        }
        hrow[lane + i * 32] = make_ushort4(h[0], h[1], h[2], h[3]);
        lrow[lane + i * 32] = make_ushort4(l[0], l[1], l[2], l[3]);
    }
}

// ---------------------------------------------------------------------------
// Launch (5 launches; 2 and 4 are the GEMMs)
// ---------------------------------------------------------------------------
extern "C" void kernel_launch(void* const* d_in, const int* in_sizes, int n_in,
                              void* d_out, int out_size)
{
    const float* x  = (const float*)d_in[0];
    const float* Wq = (const float*)d_in[1];
    const float* bq = (const float*)d_in[2];
    const float* Wk = (const float*)d_in[3];
    const float* bk = (const float*)d_in[4];
    const float* Wv = (const float*)d_in[5];
    const float* bv = (const float*)d_in[6];
    const float* Wo = (const float*)d_in[7];
    const float* bo = (const float*)d_in[8];

    float *q, *k, *v;
    __nv_bfloat16 *xh, *xl, *ch, *cl, *wh, *wl;
    cudaGetSymbolAddress((void**)&q,   g_q);
    cudaGetSymbolAddress((void**)&k,   g_k);
    cudaGetSymbolAddress((void**)&v,   g_v);
    cudaGetSymbolAddress((void**)&xh,  g_x_hi);
    cudaGetSymbolAddress((void**)&xl,  g_x_lo);
    cudaGetSymbolAddress((void**)&ch,  g_ctx_hi);
    cudaGetSymbolAddress((void**)&cl,  g_ctx_lo);
    cudaGetSymbolAddress((void**)&wh,  g_w_hi);
    cudaGetSymbolAddress((void**)&wl,  g_w_lo);

    cudaFuncSetAttribute(gemm_bf16x3, cudaFuncAttributeMaxDynamicSharedMemorySize, GEMM_SMEM);
    cudaFuncSetAttribute(local_attn,  cudaFuncAttributeMaxDynamicSharedMemorySize, ATTN_SMEM);

    const int nx4 = MM * CC / 4;
    const int nw4 = CC * CC / 4;
    const size_t WSZ = (size_t)CC * CC;

    // 0: split x
    split_bf16<<<dim3(nx4 / 256, 1), 256>>>(x, x, x, x, xh, xl, nx4);
    // 1: split Wq|Wk|Wv|Wo -> segments 0..3
    split_bf16<<<dim3(nw4 / 256, 4), 256>>>(Wq, Wk, Wv, Wo, wh, wl, nw4);
    // 2: fused QKV GEMM (persistent, 3072 tiles, nblk=48)
    gemm_bf16x3<<<GRID_PERSIST, 256, GEMM_SMEM>>>(xh, xl, wh, wl,
                                                  bq, bk, bv, q, k, v,
                                                  (MM / BM) * 48, 48);
    // 3: smem-tiled attention (writes ctx hi/lo)
    local_attn<<<dim3(TT / GG, BB), 256, ATTN_SMEM>>>(q, k, v, ch, cl);
    // 4: output projection (persistent, 1024 tiles, nblk=16)
    gemm_bf16x3<<<GRID_PERSIST, 256, GEMM_SMEM>>>(ch, cl, wh + 3 * WSZ, wl + 3 * WSZ,
                                                  bo, bo, bo,
                                                  (float*)d_out, (float*)d_out, (float*)d_out,
                                                  (MM / BM) * 16, 16);
}

// round 11
// speedup vs baseline: 2.4448x; 1.3170x over previous
#include <cuda_runtime.h>
#include <cuda_bf16.h>
#include <cuda_fp16.h>
#include <math.h>
#include <cstdint>

// Problem constants (LocalAttention: B=4, T=2048, C=1024, WIN=16)
#define BB   4
#define TT   2048
#define CC   1024
#define HALF 8
#define WW   17
#define MM   8192

// GEMM tiling: CTA tile 128x64, warp tile 32x32, 8 warps (4M x 2N)
#define BM 128
#define BN 64
#define BKK 32                    // fp16 K elems per stage
#define NIT (CC / BKK)            // 32 k-iterations
#define ATILE_B 8192              // 128 rows x 32 f16 x 2B
#define BTILE_B 4096              // 64 rows x 32 f16 x 2B
#define QSTAGE_B (2 * ATILE_B + BTILE_B)      // 20480 (Ah, Al, Wh)
#define GEMM_SMEM (4 * QSTAGE_B)  // 81920
#define GRID_PERSIST 296          // 2 CTAs per SM

// Attention: block = 8 t-positions, C chunked into 4x256, double buffer
#define GG   8
#define CHW  256
#define NCH  4
#define WROWS 24
#define ATTN_SMEM (2 * WROWS * CHW * 4)   // 49152

// ---------------------------------------------------------------------------
// Scratch (device globals: allocation-free rule)
// ---------------------------------------------------------------------------
__device__ float g_q[MM * CC];
__device__ float g_k[MM * CC];
__device__ float g_v[MM * CC];
__device__ __half g_xh[MM * CC];
__device__ __half g_xl[MM * CC];
__device__ __half g_ch[MM * CC];
__device__ __half g_cl[MM * CC];
__device__ __half g_w16[4 * CC * CC];   // Wq, Wk, Wv, Wo (single fp16)

// ---------------------------------------------------------------------------
// PTX helpers (sm_80+ base-target instructions only)
// ---------------------------------------------------------------------------
__device__ __forceinline__ uint32_t smem_u32(const void* p) {
    uint32_t a;
    asm("{ .reg .u64 t; cvta.to.shared.u64 t, %1; cvt.u32.u64 %0, t; }" : "=r"(a) : "l"(p));
    return a;
}
__device__ __forceinline__ void cp_async16(uint32_t dst, const void* src) {
    asm volatile("cp.async.cg.shared.global [%0], [%1], 16;" :: "r"(dst), "l"(src));
}
__device__ __forceinline__ void cp_commit() { asm volatile("cp.async.commit_group;"); }
template <int N>
__device__ __forceinline__ void cp_wait() { asm volatile("cp.async.wait_group %0;" :: "n"(N)); }

__device__ __forceinline__ void ldsm_x4(uint32_t& r0, uint32_t& r1, uint32_t& r2, uint32_t& r3,
                                        uint32_t addr) {
    asm volatile("ldmatrix.sync.aligned.m8n8.x4.shared.b16 {%0,%1,%2,%3}, [%4];"
                 : "=r"(r0), "=r"(r1), "=r"(r2), "=r"(r3) : "r"(addr));
}
__device__ __forceinline__ void mma_f16(float* d, const uint32_t* a, uint32_t b0, uint32_t b1) {
    asm volatile(
        "mma.sync.aligned.m16n8k16.row.col.f32.f16.f16.f32 "
        "{%0,%1,%2,%3}, {%4,%5,%6,%7}, {%8,%9}, {%0,%1,%2,%3};"
        : "+f"(d[0]), "+f"(d[1]), "+f"(d[2]), "+f"(d[3])
        : "r"(a[0]), "r"(a[1]), "r"(a[2]), "r"(a[3]), "r"(b0), "r"(b1));
}

// Swizzle on 64B logical rows (conflict-free ldmatrix + STS16)
#define SWZ(off) ((off) ^ (((off) >> 3) & 0x70))

__device__ __forceinline__ uint32_t ldsm_addr(uint32_t tile_base, int row0, int chunk0, int lane) {
    int row   = row0 + (lane & 15);
    int chunk = chunk0 + (lane >> 4);
    uint32_t off = (uint32_t)row * 64 + (uint32_t)chunk * 16;
    return tile_base + SWZ(off);
}

// ---------------------------------------------------------------------------
// fp32 -> fp16 hi/lo split (x and — via attention — ctx path)
// ---------------------------------------------------------------------------
__global__ __launch_bounds__(256)
void split_f16x2(const float* __restrict__ src,
                 __half* __restrict__ hi, __half* __restrict__ lo, int n4)
{
    int i = blockIdx.x * blockDim.x + threadIdx.x;
    if (i >= n4) return;
    float4 v = ((const float4*)src)[i];
    float f[4] = {v.x, v.y, v.z, v.w};
    __half h[4], l[4];
#pragma unroll
    for (int j = 0; j < 4; j++) {
        h[j] = __float2half(f[j]);
        l[j] = __float2half(f[j] - __half2float(h[j]));
    }
    ((ushort4*)hi)[i] = make_ushort4(*(unsigned short*)&h[0], *(unsigned short*)&h[1],
                                     *(unsigned short*)&h[2], *(unsigned short*)&h[3]);
    ((ushort4*)lo)[i] = make_ushort4(*(unsigned short*)&l[0], *(unsigned short*)&l[1],
                                     *(unsigned short*)&l[2], *(unsigned short*)&l[3]);
}

// fp32 -> single fp16 (weights); blockIdx.y selects among 4 sources.
__global__ __launch_bounds__(256)
void conv_f16(const float* __restrict__ s0, const float* __restrict__ s1,
              const float* __restrict__ s2, const float* __restrict__ s3,
              __half* __restrict__ out, int n4)
{
    const int w = blockIdx.y;
    const float* srcs[4] = {s0, s1, s2, s3};
    int i = blockIdx.x * blockDim.x + threadIdx.x;
    if (i >= n4) return;
    float4 v = ((const float4*)srcs[w])[i];
    __half h[4] = {__float2half(v.x), __float2half(v.y), __float2half(v.z), __float2half(v.w)};
    ((ushort4*)out)[(size_t)w * n4 + i] =
        make_ushort4(*(unsigned short*)&h[0], *(unsigned short*)&h[1],
                     *(unsigned short*)&h[2], *(unsigned short*)&h[3]);
}

// ---------------------------------------------------------------------------
// Persistent fp16 2-term NT GEMM, 128x64 CTA tile, 2 CTAs/SM.
// out[m,n] = sum_k (Ah+Al)[m,k]*Wh[n,k] + bias[n]
// nblk = weight 64-col blocks (48 fused QKV, 16 Wo); which = nb>>4.
// ---------------------------------------------------------------------------
__global__ __launch_bounds__(256, 2)
void gemm_f16x2(const __half* __restrict__ Ah, const __half* __restrict__ Al,
                const __half* __restrict__ Wh,
                const float* __restrict__ b0, const float* __restrict__ b1,
                const float* __restrict__ b2,
                float* __restrict__ o0, float* __restrict__ o1, float* __restrict__ o2,
                int ntiles, int nblk)
{
    extern __shared__ char sm[];
    const uint32_t sbase = smem_u32(sm);
    const int tid   = threadIdx.x;
    const int lane  = tid & 31;
    const int warp  = tid >> 5;
    const int warpM = warp >> 1;
    const int warpN = warp & 1;

    const int larow = tid >> 1;
    const int lac0  = (tid & 1) * 2;
    uint32_t daphys[2];
#pragma unroll
    for (int i = 0; i < 2; i++) {
        uint32_t off = (uint32_t)larow * 64 + (uint32_t)(lac0 + i) * 16;
        daphys[i] = SWZ(off);
    }
    const int lbrow = tid >> 2;
    const int lbc   = tid & 3;
    const uint32_t dbphys = SWZ((uint32_t)lbrow * 64 + (uint32_t)lbc * 16);

    for (int tile = blockIdx.x; tile < ntiles; tile += gridDim.x) {
        const int mb = tile / nblk;
        const int nb = tile - mb * nblk;
        const int bm = mb * BM;
        const int which = nb >> 4;
        const int col0  = (nb & 15) * BN;
        const float* bias = (which == 0) ? b0 : ((which == 1) ? b1 : b2);
        float* Cout       = (which == 0) ? o0 : ((which == 1) ? o1 : o2);

        const __half* gA[2] = {
            Ah + (size_t)(bm + larow) * CC,
            Al + (size_t)(bm + larow) * CC
        };
        const __half* gW = Wh + (size_t)(nb * BN + lbrow) * CC;

#define ISSUE_STAGE(s, kc) do { \
    uint32_t stg_ = sbase + (uint32_t)(s) * QSTAGE_B; \
    _Pragma("unroll") \
    for (int h_ = 0; h_ < 2; h_++) { \
        _Pragma("unroll") \
        for (int i_ = 0; i_ < 2; i_++) { \
            cp_async16(stg_ + h_ * ATILE_B + daphys[i_], gA[h_] + (kc) + (lac0 + i_) * 8); \
        } \
    } \
    cp_async16(stg_ + 2 * ATILE_B + dbphys, gW + (kc) + lbc * 8); \
    cp_commit(); \
} while (0)

        float acc[2][4][4];
#pragma unroll
        for (int mt = 0; mt < 2; mt++)
#pragma unroll
            for (int nt = 0; nt < 4; nt++)
#pragma unroll
                for (int r = 0; r < 4; r++) acc[mt][nt][r] = 0.f;

        ISSUE_STAGE(0, 0);
        ISSUE_STAGE(1, 32);
        ISSUE_STAGE(2, 64);

        for (int it = 0; it < NIT; it++) {
            cp_wait<2>();
            __syncthreads();
            if (it + 3 < NIT) { ISSUE_STAGE((it + 3) & 3, (it + 3) * BKK); }
            else              { cp_commit(); }

            const uint32_t stg = sbase + (uint32_t)(it & 3) * QSTAGE_B;
#pragma unroll
            for (int g = 0; g < 2; g++) {
                uint32_t afr[2][2][4];           // [mt][h/l][reg]
#pragma unroll
                for (int mt = 0; mt < 2; mt++)
#pragma unroll
                    for (int hl = 0; hl < 2; hl++) {
                        uint32_t ad = ldsm_addr(stg + hl * ATILE_B,
                                                warpM * 32 + mt * 16, 2 * g, lane);
                        ldsm_x4(afr[mt][hl][0], afr[mt][hl][1], afr[mt][hl][2], afr[mt][hl][3], ad);
                    }
                uint32_t bfr[2][4];              // [gp][reg]
#pragma unroll
                for (int gp = 0; gp < 2; gp++) {
                    uint32_t ad = ldsm_addr(stg + 2 * ATILE_B,
                                            warpN * 32 + gp * 16, 2 * g, lane);
                    ldsm_x4(bfr[gp][0], bfr[gp][1], bfr[gp][2], bfr[gp][3], ad);
                }
#pragma unroll
                for (int mt = 0; mt < 2; mt++)
#pragma unroll
                    for (int gp = 0; gp < 2; gp++) {
                        mma_f16(acc[mt][gp * 2 + 0], afr[mt][0], bfr[gp][0], bfr[gp][2]);
                        mma_f16(acc[mt][gp * 2 + 1], afr[mt][0], bfr[gp][1], bfr[gp][3]);
                        mma_f16(acc[mt][gp * 2 + 0], afr[mt][1], bfr[gp][0], bfr[gp][2]);
                        mma_f16(acc[mt][gp * 2 + 1], afr[mt][1], bfr[gp][1], bfr[gp][3]);
                    }
            }
        }

#pragma unroll
        for (int mt = 0; mt < 2; mt++) {
            const int row0 = bm + warpM * 32 + mt * 16 + (lane >> 2);
#pragma unroll
            for (int nt = 0; nt < 4; nt++) {
                const int col = col0 + warpN * 32 + nt * 8 + (lane & 3) * 2;
                const float c0 = bias[col], c1 = bias[col + 1];
                float2 v0 = make_float2(acc[mt][nt][0] + c0, acc[mt][nt][1] + c1);
                float2 v1 = make_float2(acc[mt][nt][2] + c0, acc[mt][nt][3] + c1);
                *(float2*)(Cout + (size_t)row0 * CC + col)       = v0;
                *(float2*)(Cout + (size_t)(row0 + 8) * CC + col) = v1;
            }
        }
#undef ISSUE_STAGE
    }
}

// ---------------------------------------------------------------------------
// Chunked smem local attention: block = 8 t (1 warp each), C in 4x256 chunks,
// 2x24KB double-buffered window via cp.async. Writes ctx as fp16 hi/lo.
// ---------------------------------------------------------------------------
__device__ __forceinline__ void store_hl(__half* ch, __half* cl, size_t off, float4 a) {
    float f[4] = {a.x, a.y, a.z, a.w};
    unsigned short h[4], l[4];
#pragma unroll
    for (int c = 0; c < 4; c++) {
        __half hb = __float2half(f[c]);
        __half lb = __float2half(f[c] - __half2float(hb));
        h[c] = *(unsigned short*)&hb;
        l[c] = *(unsigned short*)&lb;
    }
    *(ushort4*)(ch + off) = make_ushort4(h[0], h[1], h[2], h[3]);
    *(ushort4*)(cl + off) = make_ushort4(l[0], l[1], l[2], l[3]);
}

#define ATTN_ISSUE(dstu32, srcp, c) do { \
    _Pragma("unroll") \
    for (int i_ = 0; i_ < 6; i_++) { \
        int idx_ = i_ * 256 + tid; \
        int r_ = idx_ >> 6, f4_ = idx_ & 63; \
        int trow_ = t0 - HALF + r_; \
        if (trow_ >= 0 && trow_ < TT) \
            cp_async16((dstu32) + ((uint32_t)r_ * CHW + f4_ * 4) * 4, \
                       (srcp) + base + (size_t)trow_ * CC + (c) * CHW + f4_ * 4); \
    } \
    cp_commit(); \
} while (0)

__global__ __launch_bounds__(256)
void local_attn(const float* __restrict__ q, const float* __restrict__ k,
                const float* __restrict__ v,
                __half* __restrict__ ch, __half* __restrict__ cl)
{
    extern __shared__ float sh[];
    float* bufp[2] = { sh, sh + WROWS * CHW };
    __shared__ float swgt[GG][WW];

    const int b    = blockIdx.y;
    const int t0   = blockIdx.x * GG;
    const int tid  = threadIdx.x;
    const int warp = tid >> 5;
    const int lane = tid & 31;
    const uint32_t sb[2] = { smem_u32(bufp[0]), smem_u32(bufp[1]) };
    const size_t base = (size_t)b * TT * CC;

    const int t = t0 + warp;
    const size_t btrow = base + (size_t)t * CC;

    float p[WW];
#pragma unroll
    for (int w = 0; w < WW; w++) p[w] = 0.f;

    // ---- Score pass over K chunks ----
    ATTN_ISSUE(sb[0], k, 0);
    for (int c = 0; c < NCH; c++) {
        cp_wait<0>();
        __syncthreads();
        if (c + 1 < NCH) ATTN_ISSUE(sb[(c + 1) & 1], k, c + 1);
        const float4* kb = (const float4*)bufp[c & 1];
        const float4* qr = (const float4*)(q + btrow);
        float4 q0 = qr[c * 64 + lane];
        float4 q1 = qr[c * 64 + lane + 32];
#pragma unroll
        for (int w = 0; w < WW; w++) {
            int tt = t + w - HALF;
            if (tt < 0 || tt >= TT) continue;
            float4 k0 = kb[(warp + w) * 64 + lane];
            float4 k1 = kb[(warp + w) * 64 + lane + 32];
            p[w] += q0.x * k0.x + q0.y * k0.y + q0.z * k0.z + q0.w * k0.w
                  + q1.x * k1.x + q1.y * k1.y + q1.z * k1.z + q1.w * k1.w;
        }
    }

    // Reduce + softmax (per warp)
#pragma unroll
    for (int w = 0; w < WW; w++) {
#pragma unroll
        for (int o = 16; o; o >>= 1) p[w] += __shfl_xor_sync(0xffffffffu, p[w], o);
    }
    if (lane == 0) {
        float mx = -1e30f;
#pragma unroll
        for (int w = 0; w < WW; w++) {
            int tt = t + w - HALF;
            p[w] = (tt >= 0 && tt < TT) ? p[w] * 0.03125f : -3.0e38f;
            mx = fmaxf(mx, p[w]);
        }
        float sum = 0.f;
#pragma unroll
        for (int w = 0; w < WW; w++) {
            float e = (p[w] > -1.0e38f) ? expf(p[w] - mx) : 0.f;
            swgt[warp][w] = e;
            sum += e;
        }
        const float inv = 1.f / sum;
#pragma unroll
        for (int w = 0; w < WW; w++) swgt[warp][w] *= inv;
    }
    __syncthreads();   // swgt visible; all warps done with K buffers
    float wgt[WW];
#pragma unroll
    for (int w = 0; w < WW; w++) wgt[w] = swgt[warp][w];

    // ---- Output pass over V chunks ----
    ATTN_ISSUE(sb[0], v, 0);
    for (int c = 0; c < NCH; c++) {
        cp_wait<0>();
        __syncthreads();
        if (c + 1 < NCH) ATTN_ISSUE(sb[(c + 1) & 1], v, c + 1);
        const float4* vb = (const float4*)bufp[c & 1];
        float4 a0 = make_float4(0.f, 0.f, 0.f, 0.f);
        float4 a1 = make_float4(0.f, 0.f, 0.f, 0.f);
#pragma unroll
        for (int w = 0; w < WW; w++) {
            int tt = t + w - HALF;
            if (tt < 0 || tt >= TT) continue;
            const float aw = wgt[w];
            float4 v0 = vb[(warp + w) * 64 + lane];
            float4 v1 = vb[(warp + w) * 64 + lane + 32];
            a0.x += aw * v0.x; a0.y += aw * v0.y; a0.z += aw * v0.z; a0.w += aw * v0.w;
            a1.x += aw * v1.x; a1.y += aw * v1.y; a1.z += aw * v1.z; a1.w += aw * v1.w;
        }
        store_hl(ch, cl, btrow + c * CHW + (size_t)lane * 4, a0);
        store_hl(ch, cl, btrow + c * CHW + (size_t)(lane + 32) * 4, a1);
    }
}

// ---------------------------------------------------------------------------
// Launch (5 launches; 2 and 4 are the GEMMs)
// ---------------------------------------------------------------------------
extern "C" void kernel_launch(void* const* d_in, const int* in_sizes, int n_in,
                              void* d_out, int out_size)
{
    const float* x  = (const float*)d_in[0];
    const float* Wq = (const float*)d_in[1];
    const float* bq = (const float*)d_in[2];
    const float* Wk = (const float*)d_in[3];
    const float* bk = (const float*)d_in[4];
    const float* Wv = (const float*)d_in[5];
    const float* bv = (const float*)d_in[6];
    const float* Wo = (const float*)d_in[7];
    const float* bo = (const float*)d_in[8];

    float *q, *k, *v;
    __half *xh, *xl, *ch, *cl, *w16;
    cudaGetSymbolAddress((void**)&q,   g_q);
    cudaGetSymbolAddress((void**)&k,   g_k);
    cudaGetSymbolAddress((void**)&v,   g_v);
    cudaGetSymbolAddress((void**)&xh,  g_xh);
    cudaGetSymbolAddress((void**)&xl,  g_xl);
    cudaGetSymbolAddress((void**)&ch,  g_ch);
    cudaGetSymbolAddress((void**)&cl,  g_cl);
    cudaGetSymbolAddress((void**)&w16, g_w16);

    cudaFuncSetAttribute(gemm_f16x2, cudaFuncAttributeMaxDynamicSharedMemorySize, GEMM_SMEM);
    cudaFuncSetAttribute(local_attn, cudaFuncAttributeMaxDynamicSharedMemorySize, ATTN_SMEM);

    const int nx4 = MM * CC / 4;
    const int nw4 = CC * CC / 4;
    const size_t WSZ = (size_t)CC * CC;

    // 0: split x -> fp16 hi/lo
    split_f16x2<<<nx4 / 256, 256>>>(x, xh, xl, nx4);
    // 1: convert Wq|Wk|Wv|Wo -> single fp16 segments 0..3
    conv_f16<<<dim3(nw4 / 256, 4), 256>>>(Wq, Wk, Wv, Wo, w16, nw4);
    // 2: fused QKV GEMM (persistent, 3072 tiles, nblk=48)
    gemm_f16x2<<<GRID_PERSIST, 256, GEMM_SMEM>>>(xh, xl, w16,
                                                 bq, bk, bv, q, k, v,
                                                 (MM / BM) * 48, 48);
    // 3: chunked attention (writes ctx fp16 hi/lo)
    local_attn<<<dim3(TT / GG, BB), 256, ATTN_SMEM>>>(q, k, v, ch, cl);
    // 4: output projection (persistent, 1024 tiles, nblk=16)
    gemm_f16x2<<<GRID_PERSIST, 256, GEMM_SMEM>>>(ch, cl, w16 + 3 * WSZ,
                                                 bo, bo, bo,
                                                 (float*)d_out, (float*)d_out, (float*)d_out,
                                                 (MM / BM) * 16, 16);
}